// round 14
// baseline (speedup 1.0000x reference)
#include <cuda_runtime.h>
#include <cstdint>

#define Nn 4096
#define WORDS 128          // 4096 bits / 32
#define TI 16              // i-rows per agg block
#define JSPLIT 4           // j-range split per tile
#define NTILES (Nn / TI)   // 256
#define AGG_BLOCKS (NTILES * JSPLIT)   // 1024
#define PACK_BLOCKS 4096

// Scratch (device globals — no allocation allowed). All mutable state is
// re-zeroed by fixup_kernel at the END of every call (zero-init covers call 1).
__device__ __align__(16) uint32_t g_bitsR[Nn * WORDS];  // row-major bitsets
__device__ __align__(16) uint32_t g_w0[Nn];             // word-0 plane (fast test)
__device__ __align__(16) float g_e[Nn];    // row sums of edge_features
__device__ __align__(16) float g_agg[Nn];  // exact aggregated[i] (verification)
__device__ float g_S;                      // sum of all e[j]
__device__ int   g_tile_cnt[NTILES];       // per-tile chunk-completion counters
__device__ int   g_ndev;                   // deviation count
__device__ int   g_devi[Nn];               // deviation indices
__device__ float g_devv[Nn];               // deviation values

// ---------------------------------------------------------------------------
// K1: pack A (FMA packing, diag cleared at write) + rowsum E (also accumulate
// the global scalar S = sum(e) via one atomicAdd per row-block).
// ---------------------------------------------------------------------------
__global__ void prep_kernel(const float* __restrict__ A,
                            const float* __restrict__ E) {
    if (blockIdx.x < PACK_BLOCKS) {
        int lane = threadIdx.x & 31;
        int warpid = blockIdx.x * 8 + (threadIdx.x >> 5);   // 0..32767
        const int NW = PACK_BLOCKS * 8;                     // 32768 warps
        unsigned q = lane >> 2;                             // word-in-group (0..7)
        unsigned grpmask = 0xFu << (q << 2);
        unsigned sh = (lane & 3) * 8;
        #pragma unroll
        for (int o = 0; o < 2; o++) {
            int gg  = warpid + o * NW;
            int j   = gg >> 4;
            int grp = gg & 15;
            int col = (grp << 8) + (lane << 3);
            const float4* p = (const float4*)(A + (size_t)j * Nn + col);
            float4 v0 = __ldcs(p);
            float4 v1 = __ldcs(p + 1);
            float f = v0.x;
            f = fmaf(v0.y,   2.f, f);
            f = fmaf(v0.z,   4.f, f);
            f = fmaf(v0.w,   8.f, f);
            f = fmaf(v1.x,  16.f, f);
            f = fmaf(v1.y,  32.f, f);
            f = fmaf(v1.z,  64.f, f);
            f = fmaf(v1.w, 128.f, f);
            unsigned byte = (unsigned)f;          // exact: distinct powers of 2
            unsigned word = __reduce_or_sync(grpmask, byte << sh);
            if ((lane & 3) == 0) {
                int w = (grp << 3) + (int)q;
                if (w == (j >> 5)) word &= ~(1u << (j & 31));   // clear diag bit
                g_bitsR[j * WORDS + w] = word;
                if (w == 0) g_w0[j] = word;
            }
        }
    } else {
        int j = blockIdx.x - PACK_BLOCKS;
        const float4* row = (const float4*)(E + (size_t)j * Nn);
        int tid = threadIdx.x;
        float s = 0.f;
        #pragma unroll
        for (int k = 0; k < 4; k++) {
            float4 v = __ldcs(row + tid + 256 * k);
            s += (v.x + v.y) + (v.z + v.w);
        }
        s += __shfl_down_sync(0xffffffffu, s, 16);
        s += __shfl_down_sync(0xffffffffu, s, 8);
        s += __shfl_down_sync(0xffffffffu, s, 4);
        s += __shfl_down_sync(0xffffffffu, s, 2);
        s += __shfl_down_sync(0xffffffffu, s, 1);
        __shared__ float sp[8];
        int lane = tid & 31, wid = tid >> 5;
        if (lane == 0) sp[wid] = s;
        __syncthreads();
        if (tid == 0) {
            float t = 0.f;
            #pragma unroll
            for (int k = 0; k < 8; k++) t += sp[k];
            g_e[j] = t;
            atomicAdd(&g_S, t);
        }
    }
}

// ---------------------------------------------------------------------------
// K2 (independent agg + gemv, interleaved 1:4 so every wave mixes ALU-bound
// agg with DRAM-bound gemv):
//  b%5==0 : agg block — exact agg[i] (subtract-on-miss bitsets). The LAST
//           chunk per tile computes delta[i] = (S - e[i]) - agg[i] and appends
//           any |delta| > 0.5 to the deviation list (expected: none; noise
//           level is ~1e-2, a real deviation is ~|e| ~ 64).
//  else    : gemv row o — out[o] = S*rowsum(W[o]) - dot(W[o], e) + b[o].
//           NO dependency on agg. K3 applies the (expected-empty) correction.
// ---------------------------------------------------------------------------
__global__ void main2_kernel(const float* __restrict__ Wm,
                             const float* __restrict__ bias,
                             float* __restrict__ out) {
    int b = blockIdx.x;
    int tid = threadIdx.x;

    if (b % 5 == 0) {
        int id = b / 5;                   // 0..AGG_BLOCKS-1
        int tile  = id & (NTILES - 1);
        int chunk = id >> 8;              // 0..JSPLIT-1
        int i0 = tile * TI;

        __shared__ uint32_t sBi[TI * WORDS];
        __shared__ int sNe[TI];
        __shared__ float sPart[8][TI];
        __shared__ int sLast;

        if (tid < TI) sNe[tid] = 0;
        __syncthreads();
        {   // coalesced i-tile load: 8KB contiguous
            const uint4* src = (const uint4*)(g_bitsR + (size_t)i0 * WORDS);
            uint4* dst = (uint4*)sBi;
            #pragma unroll
            for (int k = 0; k < (TI * WORDS / 4) / 256; k++) {
                uint4 v = src[tid + 256 * k];
                dst[tid + 256 * k] = v;
                if (v.x | v.y | v.z | v.w) sNe[(tid + 256 * k) >> 5] = 1;
            }
        }
        __syncthreads();

        int jBeg = chunk * (Nn / JSPLIT);
        int jEnd = jBeg + (Nn / JSPLIT);

        float sumE = 0.f;
        for (int j = jBeg + tid; j < jEnd; j += blockDim.x) sumE += g_e[j];

        uint32_t bi0[TI];
        float acc[TI];
        #pragma unroll
        for (int r = 0; r < TI; r++) { bi0[r] = sBi[r * WORDS]; acc[r] = sumE; }

        for (int j = jBeg + tid; j < jEnd; j += blockDim.x) {
            uint32_t b0 = g_w0[j];
            unsigned zmask = 0;
            #pragma unroll
            for (int r = 0; r < TI; r++) {
                if (!(bi0[r] & b0)) zmask |= (1u << r);
            }
            if (zmask) {                  // rare (~1e-4 per pair)
                float e = g_e[j];
                const uint32_t* bj = g_bitsR + (size_t)j * WORDS;
                do {
                    int r = __ffs(zmask) - 1;
                    zmask &= zmask - 1;
                    bool hit = false;
                    for (int w = 1; w < WORDS; w++)
                        if (sBi[r * WORDS + w] & bj[w]) { hit = true; break; }
                    if (!hit) acc[r] -= e;
                } while (zmask);
            }
        }

        int lane = tid & 31, wid = tid >> 5;
        #pragma unroll
        for (int r = 0; r < TI; r++) {
            float v = acc[r];
            v += __shfl_down_sync(0xffffffffu, v, 16);
            v += __shfl_down_sync(0xffffffffu, v, 8);
            v += __shfl_down_sync(0xffffffffu, v, 4);
            v += __shfl_down_sync(0xffffffffu, v, 2);
            v += __shfl_down_sync(0xffffffffu, v, 1);
            if (lane == 0) sPart[wid][r] = v;
        }
        __syncthreads();
        if (tid < TI) {
            float s = 0.f;
            #pragma unroll
            for (int w = 0; w < 8; w++) s += sPart[w][tid];
            int i = i0 + tid;
            if (i >= jBeg && i < jEnd && sNe[tid]) s -= g_e[i];  // diag fix
            atomicAdd(&g_agg[i], s);
            __threadfence();              // release our contribution
        }
        __syncthreads();
        if (tid == 0) {
            int old = atomicAdd(&g_tile_cnt[tile], 1);
            sLast = (old == JSPLIT - 1);
        }
        __syncthreads();
        if (sLast && tid < TI) {
            __threadfence();              // acquire other chunks' atomics
            int i = i0 + tid;
            float a;
            asm volatile("ld.global.cg.f32 %0, [%1];" : "=f"(a) : "l"(&g_agg[i]));
            float delta = (g_S - g_e[i]) - a;
            if (fabsf(delta) > 0.5f) {
                int pos = atomicAdd(&g_ndev, 1);
                g_devi[pos] = i;
                g_devv[pos] = delta;
            }
        }
    } else {
        // ---- gemv row o: no dependency on agg ----
        int o = b - b / 5 - 1;
        const float4* wr = (const float4*)(Wm + (size_t)o * Nn);
        const float4* er = (const float4*)g_e;
        float4 w0 = __ldcs(wr + tid);
        float4 w1 = __ldcs(wr + tid + 256);
        float4 w2 = __ldcs(wr + tid + 512);
        float4 w3 = __ldcs(wr + tid + 768);
        float4 e0 = er[tid];
        float4 e1 = er[tid + 256];
        float4 e2 = er[tid + 512];
        float4 e3 = er[tid + 768];
        // dot(W,e) and rowsum(W) in one pass
        float d = w0.x * e0.x + w0.y * e0.y + w0.z * e0.z + w0.w * e0.w;
        d += w1.x * e1.x + w1.y * e1.y + w1.z * e1.z + w1.w * e1.w;
        d += w2.x * e2.x + w2.y * e2.y + w2.z * e2.z + w2.w * e2.w;
        d += w3.x * e3.x + w3.y * e3.y + w3.z * e3.z + w3.w * e3.w;
        float r = (w0.x + w0.y) + (w0.z + w0.w);
        r += (w1.x + w1.y) + (w1.z + w1.w);
        r += (w2.x + w2.y) + (w2.z + w2.w);
        r += (w3.x + w3.y) + (w3.z + w3.w);

        d += __shfl_down_sync(0xffffffffu, d, 16);
        r += __shfl_down_sync(0xffffffffu, r, 16);
        d += __shfl_down_sync(0xffffffffu, d, 8);
        r += __shfl_down_sync(0xffffffffu, r, 8);
        d += __shfl_down_sync(0xffffffffu, d, 4);
        r += __shfl_down_sync(0xffffffffu, r, 4);
        d += __shfl_down_sync(0xffffffffu, d, 2);
        r += __shfl_down_sync(0xffffffffu, r, 2);
        d += __shfl_down_sync(0xffffffffu, d, 1);
        r += __shfl_down_sync(0xffffffffu, r, 1);
        __shared__ float spd[8], spr[8];
        int lane = tid & 31, wid = tid >> 5;
        if (lane == 0) { spd[wid] = d; spr[wid] = r; }
        __syncthreads();
        if (tid == 0) {
            float td = 0.f, tr = 0.f;
            #pragma unroll
            for (int k = 0; k < 8; k++) { td += spd[k]; tr += spr[k]; }
            out[o] = g_S * tr - td + bias[o];
        }
    }
}

// ---------------------------------------------------------------------------
// K3 (single block): apply deviation corrections (expected: zero entries),
// then re-zero all mutable state for the next graph replay.
// ---------------------------------------------------------------------------
__global__ void fixup_kernel(const float* __restrict__ Wm,
                             float* __restrict__ out) {
    int tid = threadIdx.x;
    int nd = g_ndev;                      // same value seen by all threads
    if (nd > 0) {
        for (int o = tid; o < Nn; o += 256) {
            float c = 0.f;
            for (int k = 0; k < nd; k++)
                c += g_devv[k] * Wm[(size_t)o * Nn + g_devi[k]];
            out[o] -= c;
        }
    }
    __syncthreads();
    // reset state for next call
    float4 z4 = make_float4(0.f, 0.f, 0.f, 0.f);
    float4* a4 = (float4*)g_agg;
    #pragma unroll
    for (int k = 0; k < 4; k++) a4[tid + 256 * k] = z4;
    if (tid < NTILES) g_tile_cnt[tid] = 0;
    if (tid == 0) { g_S = 0.f; g_ndev = 0; }
}

extern "C" void kernel_launch(void* const* d_in, const int* in_sizes, int n_in,
                              void* d_out, int out_size) {
    const float* A  = (const float*)d_in[0];  // adjacency [N,N]
    const float* E  = (const float*)d_in[1];  // edge_features [N,F]
    const float* Wm = (const float*)d_in[2];  // W [OUT,N]
    const float* b  = (const float*)d_in[3];  // b [OUT]
    float* out = (float*)d_out;

    prep_kernel<<<PACK_BLOCKS + Nn, 256>>>(A, E);
    main2_kernel<<<AGG_BLOCKS + Nn, 256>>>(Wm, b, out);
    fixup_kernel<<<1, 256>>>(Wm, out);
}

// round 16
// speedup vs baseline: 1.0261x; 1.0261x over previous
#include <cuda_runtime.h>
#include <cstdint>

#define Nn 4096
#define WORDS 128
#define TI 16              // i-rows per agg block
#define JSPLIT 4
#define NTILES (Nn / TI)   // 256
#define AGG_BLOCKS (NTILES * JSPLIT)     // 1024
#define ROWS_PER_GEMV 4
#define GEMV_BLOCKS (Nn / ROWS_PER_GEMV) // 1024
#define GRID2 (AGG_BLOCKS + GEMV_BLOCKS) // 2048
#define PACK_BLOCKS 4096

// Device scratch. All mutable state re-zeroed by the last block each call.
__device__ __align__(16) uint32_t g_bitsR[Nn * WORDS];
__device__ __align__(16) uint32_t g_w0[Nn];
__device__ __align__(16) float g_e[Nn];
__device__ __align__(16) float g_agg[Nn];
__device__ float g_S;
__device__ int   g_tile_cnt[NTILES];
__device__ int   g_ndev;
__device__ int   g_devi[Nn];
__device__ float g_devv[Nn];
__device__ unsigned g_done;

// ---------------------------------------------------------------------------
// K1: even blocks pack A (FMA packing, diag cleared at write), odd blocks
// row-sum E (+ accumulate S). Interleaved so every wave mixes the
// store-bearing pack stream with the pure-read rowsum stream.
// ---------------------------------------------------------------------------
__global__ void prep_kernel(const float* __restrict__ A,
                            const float* __restrict__ E) {
    if ((blockIdx.x & 1) == 0) {
        int pb = blockIdx.x >> 1;                           // 0..4095
        int lane = threadIdx.x & 31;
        int warpid = pb * 8 + (threadIdx.x >> 5);           // 0..32767
        const int NW = PACK_BLOCKS * 8;
        unsigned q = lane >> 2;
        unsigned grpmask = 0xFu << (q << 2);
        unsigned sh = (lane & 3) * 8;
        #pragma unroll
        for (int o = 0; o < 2; o++) {
            int gg  = warpid + o * NW;
            int j   = gg >> 4;
            int grp = gg & 15;
            int col = (grp << 8) + (lane << 3);
            const float4* p = (const float4*)(A + (size_t)j * Nn + col);
            float4 v0 = __ldcs(p);
            float4 v1 = __ldcs(p + 1);
            float f = v0.x;
            f = fmaf(v0.y,   2.f, f);
            f = fmaf(v0.z,   4.f, f);
            f = fmaf(v0.w,   8.f, f);
            f = fmaf(v1.x,  16.f, f);
            f = fmaf(v1.y,  32.f, f);
            f = fmaf(v1.z,  64.f, f);
            f = fmaf(v1.w, 128.f, f);
            unsigned byte = (unsigned)f;
            unsigned word = __reduce_or_sync(grpmask, byte << sh);
            if ((lane & 3) == 0) {
                int w = (grp << 3) + (int)q;
                if (w == (j >> 5)) word &= ~(1u << (j & 31));
                g_bitsR[j * WORDS + w] = word;
                if (w == 0) g_w0[j] = word;
            }
        }
    } else {
        int j = blockIdx.x >> 1;
        const float4* row = (const float4*)(E + (size_t)j * Nn);
        int tid = threadIdx.x;
        float s = 0.f;
        #pragma unroll
        for (int k = 0; k < 4; k++) {
            float4 v = __ldcs(row + tid + 256 * k);
            s += (v.x + v.y) + (v.z + v.w);
        }
        s += __shfl_down_sync(0xffffffffu, s, 16);
        s += __shfl_down_sync(0xffffffffu, s, 8);
        s += __shfl_down_sync(0xffffffffu, s, 4);
        s += __shfl_down_sync(0xffffffffu, s, 2);
        s += __shfl_down_sync(0xffffffffu, s, 1);
        __shared__ float sp[8];
        int lane = tid & 31, wid = tid >> 5;
        if (lane == 0) sp[wid] = s;
        __syncthreads();
        if (tid == 0) {
            float t = 0.f;
            #pragma unroll
            for (int k = 0; k < 8; k++) t += sp[k];
            g_e[j] = t;
            atomicAdd(&g_S, t);
        }
    }
}

// ---------------------------------------------------------------------------
// K2: even blocks agg (exact bitset verification -> deviation list),
//     odd blocks gemv (4 rows each; out = S*rowsum(W) - W@e + b, independent
//     of agg). Last block to finish applies the (expected-empty) deviation
//     correction and resets all mutable state for graph replay.
// ---------------------------------------------------------------------------
__global__ void main2_kernel(const float* __restrict__ Wm,
                             const float* __restrict__ bias,
                             float* __restrict__ out) {
    int b = blockIdx.x;
    int tid = threadIdx.x;
    __shared__ int sOld;

    if ((b & 1) == 0) {
        // ---------------- agg branch ----------------
        int id = b >> 1;                  // 0..AGG_BLOCKS-1
        int tile  = id & (NTILES - 1);
        int chunk = id >> 8;
        int i0 = tile * TI;

        __shared__ __align__(16) uint32_t sBi[TI * WORDS];
        __shared__ int sNe[TI];
        __shared__ float sPart[8][TI];
        __shared__ int sLast;

        if (tid < TI) sNe[tid] = 0;
        __syncthreads();
        {
            const uint4* src = (const uint4*)(g_bitsR + (size_t)i0 * WORDS);
            uint4* dst = (uint4*)sBi;
            #pragma unroll
            for (int k = 0; k < (TI * WORDS / 4) / 256; k++) {
                uint4 v = src[tid + 256 * k];
                dst[tid + 256 * k] = v;
                if (v.x | v.y | v.z | v.w) sNe[(tid + 256 * k) >> 5] = 1;
            }
        }
        __syncthreads();

        int jBeg = chunk * (Nn / JSPLIT);
        int jEnd = jBeg + (Nn / JSPLIT);

        float sumE = 0.f;
        for (int j = jBeg + tid; j < jEnd; j += blockDim.x) sumE += g_e[j];

        uint32_t bi0[TI];
        float acc[TI];
        #pragma unroll
        for (int r = 0; r < TI; r++) { bi0[r] = sBi[r * WORDS]; acc[r] = sumE; }

        for (int j = jBeg + tid; j < jEnd; j += blockDim.x) {
            uint32_t b0 = g_w0[j];
            unsigned zmask = 0;
            #pragma unroll
            for (int r = 0; r < TI; r++) {
                if (!(bi0[r] & b0)) zmask |= (1u << r);
            }
            if (zmask) {                  // rare (~1e-4 per pair)
                float e = g_e[j];
                const uint32_t* bj = g_bitsR + (size_t)j * WORDS;
                do {
                    int r = __ffs(zmask) - 1;
                    zmask &= zmask - 1;
                    bool hit = false;
                    for (int w = 1; w < WORDS; w++)
                        if (sBi[r * WORDS + w] & bj[w]) { hit = true; break; }
                    if (!hit) acc[r] -= e;
                } while (zmask);
            }
        }

        int lane = tid & 31, wid = tid >> 5;
        #pragma unroll
        for (int r = 0; r < TI; r++) {
            float v = acc[r];
            v += __shfl_down_sync(0xffffffffu, v, 16);
            v += __shfl_down_sync(0xffffffffu, v, 8);
            v += __shfl_down_sync(0xffffffffu, v, 4);
            v += __shfl_down_sync(0xffffffffu, v, 2);
            v += __shfl_down_sync(0xffffffffu, v, 1);
            if (lane == 0) sPart[wid][r] = v;
        }
        __syncthreads();
        if (tid < TI) {
            float s = 0.f;
            #pragma unroll
            for (int w = 0; w < 8; w++) s += sPart[w][tid];
            int i = i0 + tid;
            if (i >= jBeg && i < jEnd && sNe[tid]) s -= g_e[i];
            atomicAdd(&g_agg[i], s);
            __threadfence();
        }
        __syncthreads();
        if (tid == 0) {
            int old = atomicAdd(&g_tile_cnt[tile], 1);
            sLast = (old == JSPLIT - 1);
        }
        __syncthreads();
        if (sLast && tid < TI) {
            __threadfence();
            int i = i0 + tid;
            float a;
            asm volatile("ld.global.cg.f32 %0, [%1];" : "=f"(a) : "l"(&g_agg[i]));
            float delta = (g_S - g_e[i]) - a;
            if (fabsf(delta) > 0.5f) {     // noise ~1e-2, true miss ~|e|~64
                int pos = atomicAdd(&g_ndev, 1);
                g_devi[pos] = i;
                g_devv[pos] = delta;
            }
        }
        __syncthreads();
    } else {
        // ---------------- gemv branch: 4 rows per block ----------------
        int g = b >> 1;                   // 0..GEMV_BLOCKS-1
        int o0 = g * ROWS_PER_GEMV;
        __shared__ __align__(16) float4 se[Nn / 4];   // 16KB: full e vector
        __shared__ float spd[8][ROWS_PER_GEMV];
        __shared__ float spr[8][ROWS_PER_GEMV];
        {
            const float4* er = (const float4*)g_e;
            #pragma unroll
            for (int k = 0; k < 4; k++) se[tid + 256 * k] = er[tid + 256 * k];
        }
        __syncthreads();

        int lane = tid & 31, wid = tid >> 5;
        #pragma unroll
        for (int r = 0; r < ROWS_PER_GEMV; r++) {
            const float4* wr = (const float4*)(Wm + (size_t)(o0 + r) * Nn);
            float4 w0 = __ldcs(wr + tid);
            float4 w1 = __ldcs(wr + tid + 256);
            float4 w2 = __ldcs(wr + tid + 512);
            float4 w3 = __ldcs(wr + tid + 768);
            float4 e0 = se[tid];
            float4 e1 = se[tid + 256];
            float4 e2 = se[tid + 512];
            float4 e3 = se[tid + 768];
            float d = w0.x * e0.x + w0.y * e0.y + w0.z * e0.z + w0.w * e0.w;
            d += w1.x * e1.x + w1.y * e1.y + w1.z * e1.z + w1.w * e1.w;
            d += w2.x * e2.x + w2.y * e2.y + w2.z * e2.z + w2.w * e2.w;
            d += w3.x * e3.x + w3.y * e3.y + w3.z * e3.z + w3.w * e3.w;
            float rs = (w0.x + w0.y) + (w0.z + w0.w);
            rs += (w1.x + w1.y) + (w1.z + w1.w);
            rs += (w2.x + w2.y) + (w2.z + w2.w);
            rs += (w3.x + w3.y) + (w3.z + w3.w);
            d  += __shfl_down_sync(0xffffffffu, d, 16);
            rs += __shfl_down_sync(0xffffffffu, rs, 16);
            d  += __shfl_down_sync(0xffffffffu, d, 8);
            rs += __shfl_down_sync(0xffffffffu, rs, 8);
            d  += __shfl_down_sync(0xffffffffu, d, 4);
            rs += __shfl_down_sync(0xffffffffu, rs, 4);
            d  += __shfl_down_sync(0xffffffffu, d, 2);
            rs += __shfl_down_sync(0xffffffffu, rs, 2);
            d  += __shfl_down_sync(0xffffffffu, d, 1);
            rs += __shfl_down_sync(0xffffffffu, rs, 1);
            if (lane == 0) { spd[wid][r] = d; spr[wid][r] = rs; }
        }
        __syncthreads();
        if (tid < ROWS_PER_GEMV) {
            float td = 0.f, tr = 0.f;
            #pragma unroll
            for (int k = 0; k < 8; k++) { td += spd[k][tid]; tr += spr[k][tid]; }
            out[o0 + tid] = g_S * tr - td + bias[o0 + tid];
        }
        __syncthreads();
    }

    // ---- last-block fixup + state reset (graph-replay safe) ----
    if (tid == 0) {
        __threadfence();
        sOld = (int)atomicAdd(&g_done, 1u);
    }
    __syncthreads();
    if (sOld == GRID2 - 1) {
        __threadfence();
        int nd = g_ndev;
        if (nd > 0) {                     // expected: never
            for (int o = tid; o < Nn; o += 256) {
                float c = 0.f;
                for (int k = 0; k < nd; k++)
                    c += g_devv[k] * Wm[(size_t)o * Nn + g_devi[k]];
                out[o] -= c;
            }
        }
        __syncthreads();
        float4 z4 = make_float4(0.f, 0.f, 0.f, 0.f);
        float4* a4 = (float4*)g_agg;
        #pragma unroll
        for (int k = 0; k < 4; k++) a4[tid + 256 * k] = z4;
        if (tid < NTILES) g_tile_cnt[tid] = 0;
        if (tid == 0) { g_S = 0.f; g_ndev = 0; g_done = 0; }
    }
}

extern "C" void kernel_launch(void* const* d_in, const int* in_sizes, int n_in,
                              void* d_out, int out_size) {
    const float* A  = (const float*)d_in[0];  // adjacency [N,N]
    const float* E  = (const float*)d_in[1];  // edge_features [N,F]
    const float* Wm = (const float*)d_in[2];  // W [OUT,N]
    const float* b  = (const float*)d_in[3];  // b [OUT]
    float* out = (float*)d_out;

    prep_kernel<<<PACK_BLOCKS + Nn, 256>>>(A, E);
    main2_kernel<<<GRID2, 256>>>(Wm, b, out);
}